// round 16
// baseline (speedup 1.0000x reference)
#include <cuda_runtime.h>
#include <cuda_bf16.h>
#include <cuda_fp16.h>
#include <math.h>
#include <stdint.h>

// Problem constants
#define BB    8
#define CC    256
#define HH    56
#define WW    56
#define HIN   58
#define WIN   58
#define MTOT  25088      // B*H*W
#define NOFF  144
#define NMSK  72
#define NOM   216

// Scratch (device globals; no runtime allocation allowed)
__device__ __half g_vp[BB*HIN*WIN*CC];       // padded projected features, NHWC fp16
__device__ float g_f [MTOT*CC];              // dwconv output (pre-LN), NHWC fp32
__device__ float g_om[MTOT*NOM];             // [offset(144) | mask(72)] logits
__device__ __nv_bfloat16 g_xh[MTOT*CC];      // x-proj activations hi   [m][k]
__device__ __nv_bfloat16 g_xl[MTOT*CC];
__device__ __nv_bfloat16 g_fh[MTOT*CC];      // LN/GELU activations hi
__device__ __nv_bfloat16 g_fl[MTOT*CC];
__device__ __nv_bfloat16 g_sh[MTOT*CC];      // sampled activations hi
__device__ __nv_bfloat16 g_sl[MTOT*CC];
__device__ __nv_bfloat16 g_wth[3*65536];     // weights^T [which][n][k], hi
__device__ __nv_bfloat16 g_wtl[3*65536];     // weights^T lo

// ---------------------------------------------------------------------------
// fp32 -> bf16 hi/lo split helpers
// ---------------------------------------------------------------------------
__device__ __forceinline__ uint32_t hibits(float v) {
    uint32_t u = __float_as_uint(v);
    return (u + 0x7FFFu + ((u >> 16) & 1u)) & 0xFFFF0000u;
}
__device__ __forceinline__ uint32_t hi2(float a, float b) {
    return (hibits(a) >> 16) | (hibits(b) & 0xFFFF0000u);
}
__device__ __forceinline__ uint32_t lo2(float a, float b) {
    float la = a - __uint_as_float(hibits(a));
    float lb = b - __uint_as_float(hibits(b));
    uint32_t r;
    asm("cvt.rn.satfinite.bf16x2.f32 %0, %1, %2;" : "=r"(r) : "f"(lb), "f"(la));
    return r;
}
__device__ __forceinline__ void split1(float v, __nv_bfloat16* ph, __nv_bfloat16* pl) {
    uint32_t hb = hibits(v);
    __nv_bfloat16_raw hr; hr.x = (unsigned short)(hb >> 16);
    *ph = __nv_bfloat16(hr);
    *pl = __float2bfloat16(v - __uint_as_float(hb));
}

// mma.sync m16n8k16 bf16 -> f32
__device__ __forceinline__ void mma16816(float* c, const uint32_t* a, const uint32_t* b) {
    asm volatile(
        "mma.sync.aligned.m16n8k16.row.col.f32.bf16.bf16.f32 "
        "{%0,%1,%2,%3}, {%4,%5,%6,%7}, {%8,%9}, {%0,%1,%2,%3};"
        : "+f"(c[0]), "+f"(c[1]), "+f"(c[2]), "+f"(c[3])
        : "r"(a[0]), "r"(a[1]), "r"(a[2]), "r"(a[3]), "r"(b[0]), "r"(b[1]));
}

// ldmatrix x4
__device__ __forceinline__ void ldsm4(uint32_t* r, uint32_t a) {
    asm volatile("ldmatrix.sync.aligned.m8n8.x4.shared.b16 {%0,%1,%2,%3}, [%4];"
        : "=r"(r[0]), "=r"(r[1]), "=r"(r[2]), "=r"(r[3]) : "r"(a));
}

__device__ __forceinline__ uint32_t smem_u32(const void* p) {
    uint32_t a;
    asm("{ .reg .u64 t; cvta.to.shared.u64 t, %1; cvt.u32.u64 %0, t; }"
        : "=r"(a) : "l"(p));
    return a;
}
__device__ __forceinline__ void cpasync16(uint32_t dst, const void* src) {
    asm volatile("cp.async.cg.shared.global [%0], [%1], 16;" :: "r"(dst), "l"(src));
}
#define CP_COMMIT()  asm volatile("cp.async.commit_group;" ::: "memory")
#define CP_WAIT(n)   asm volatile("cp.async.wait_group %0;" :: "n"(n) : "memory")

// ---------------------------------------------------------------------------
// Weight prep with 32x32 smem transpose.
// ---------------------------------------------------------------------------
__global__ __launch_bounds__(256)
void prep_weights(const float* __restrict__ w_in,
                  const float* __restrict__ w_off,
                  const float* __restrict__ w_mask,
                  const float* __restrict__ w_out)
{
    __shared__ float s[32][33];
    const int which = blockIdx.x >> 6;
    const int t = blockIdx.x & 63;
    const int n0 = (t & 7) * 32, k0 = (t >> 3) * 32;
    const int tid = threadIdx.x;
    const int col = tid & 31, rowq = tid >> 5;

#pragma unroll
    for (int i = 0; i < 4; i++) {
        int kk = rowq + i * 8;
        int k = k0 + kk, n = n0 + col;
        float v;
        if (which == 0)      v = w_in[k * 256 + n];
        else if (which == 1) v = (n < NOFF) ? w_off[k * NOFF + n]
                               : (n < NOM) ? w_mask[k * NMSK + (n - NOFF)] : 0.f;
        else                 v = w_out[k * 256 + n];
        s[kk][col] = v;
    }
    __syncthreads();
#pragma unroll
    for (int i = 0; i < 4; i++) {
        int nn = rowq + i * 8;
        float v = s[col][nn];
        size_t idx = (size_t)which * 65536 + (size_t)(n0 + nn) * 256 + k0 + col;
        split1(v, &g_wth[idx], &g_wtl[idx]);
    }
}

// ---------------------------------------------------------------------------
// x (NCHW) -> g_xh/g_xl [m][k] via smem transpose.  grid = 784
// ---------------------------------------------------------------------------
__global__ __launch_bounds__(256)
void prep_x(const float* __restrict__ x)
{
    __shared__ float s[32][257];
    const int mb = blockIdx.x * 32;
    const int b = mb / 3136, hw0 = mb % 3136;
    const int lane = threadIdx.x & 31, kw = threadIdx.x >> 5;
#pragma unroll
    for (int p = 0; p < 32; p++) {
        int k = p * 8 + kw;
        s[lane][k] = x[((size_t)(b * 256 + k)) * 3136 + hw0 + lane];
    }
    __syncthreads();
    const int row = threadIdx.x >> 3, seg = threadIdx.x & 7;
    const int m = mb + row, k0 = seg * 32;
    uint32_t hi[16], lo[16];
#pragma unroll
    for (int j = 0; j < 16; j++) {
        float a = s[row][k0 + 2 * j], bv = s[row][k0 + 2 * j + 1];
        hi[j] = hi2(a, bv); lo[j] = lo2(a, bv);
    }
    uint4* dh = (uint4*)(g_xh + (size_t)m * 256 + k0);
    uint4* dl = (uint4*)(g_xl + (size_t)m * 256 + k0);
#pragma unroll
    for (int q = 0; q < 4; q++) {
        dh[q] = make_uint4(hi[4*q], hi[4*q+1], hi[4*q+2], hi[4*q+3]);
        dl[q] = make_uint4(lo[4*q], lo[4*q+1], lo[4*q+2], lo[4*q+3]);
    }
}

// ---------------------------------------------------------------------------
// Zero only the padding ring of g_vp (fp16: 2 channels per uint32 store).
// ---------------------------------------------------------------------------
__global__ void zero_border_kernel() {
    int cell = blockIdx.x;            // 0..228*8-1
    int b = cell / 228, r = cell % 228;
    int h, w;
    if (r < 58)        { h = 0;  w = r; }
    else if (r < 116)  { h = 57; w = r - 58; }
    else if (r < 172)  { h = r - 116 + 1; w = 0; }
    else               { h = r - 172 + 1; w = 57; }
    if (threadIdx.x < 128)
        ((uint32_t*)(g_vp + ((size_t)((b * 58 + h) * 58 + w)) * 256))[threadIdx.x] = 0u;
}

// ---------------------------------------------------------------------------
// Tensor-core GEMM.  Activation buffers selected by MODE inside device code.
// MODE 0 epilogue now stores fp16 vp.
// ---------------------------------------------------------------------------
#define SW_BYTES   9216    // 64 rows * 144 B
#define SM_BYTES   18432   // 128 rows * 144 B
#define STG_BYTES  55296   // 2*(SW+SM)
#define SMEM_GEMM  (2 * STG_BYTES)

template<int MODE>
__global__ __launch_bounds__(256, 2)
void gemm_mma(const float* __restrict__ bias,
              const float* __restrict__ bias2,
              float* __restrict__ Cout,
              const float* __restrict__ bn_g, const float* __restrict__ bn_b,
              const float* __restrict__ bn_mean, const float* __restrict__ bn_var)
{
    extern __shared__ char smem[];
    const uint32_t smem_b = smem_u32(smem);

    const int tid = threadIdx.x, wid = tid >> 5, lane = tid & 31;
    const int g = lane >> 2, tig = lane & 3;
    const int mat = lane >> 3, rr = lane & 7;
    const int nb0 = blockIdx.x * 64, mb0 = blockIdx.y * 128;
    const int nw = wid & 1;
    const int mw = wid >> 1;

    const __nv_bfloat16* wth = g_wth + MODE * 65536;
    const __nv_bfloat16* wtl = g_wtl + MODE * 65536;
    const __nv_bfloat16* ah = (MODE == 0) ? g_xh : (MODE == 1) ? g_fh : g_sh;
    const __nv_bfloat16* al = (MODE == 0) ? g_xl : (MODE == 1) ? g_fl : g_sl;

    float acc[2][4][4];
#pragma unroll
    for (int a = 0; a < 2; a++)
#pragma unroll
        for (int b = 0; b < 4; b++)
#pragma unroll
            for (int c = 0; c < 4; c++) acc[a][b][c] = 0.f;

    auto stage = [&](int buf, int chv) {
        const int k0c = chv * 64;
        const uint32_t base = smem_b + buf * STG_BYTES;
#pragma unroll
        for (int i = 0; i < 2; i++) {
            int idx = i * 256 + tid;
            int r = idx >> 3, seg = idx & 7;
            uint32_t so = base + (uint32_t)(r * 144 + seg * 16);
            size_t wof = (size_t)(nb0 + r) * 256 + k0c + seg * 8;
            cpasync16(so,            wth + wof);
            cpasync16(so + SW_BYTES, wtl + wof);
        }
#pragma unroll
        for (int i = 0; i < 4; i++) {
            int idx = i * 256 + tid;
            int r = idx >> 3, seg = idx & 7;
            uint32_t so = base + 2 * SW_BYTES + (uint32_t)(r * 144 + seg * 16);
            size_t mof = (size_t)(mb0 + r) * 256 + k0c + seg * 8;
            cpasync16(so,            ah + mof);
            cpasync16(so + SM_BYTES, al + mof);
        }
        CP_COMMIT();
    };

    stage(0, 0);

    for (int chv = 0; chv < 4; chv++) {
        if (chv + 1 < 4) { stage((chv + 1) & 1, chv + 1); CP_WAIT(1); }
        else             { CP_WAIT(0); }
        __syncthreads();

        const uint32_t sbuf = smem_b + (chv & 1) * STG_BYTES;
        const uint32_t sWh = sbuf;
        const uint32_t sWl = sbuf + SW_BYTES;
        const uint32_t sMh = sbuf + 2 * SW_BYTES;
        const uint32_t sMl = sbuf + 2 * SW_BYTES + SM_BYTES;

#pragma unroll
        for (int ks = 0; ks < 4; ks++) {
            const int kb = ks * 32;
            uint32_t wh[2][4], wl[2][4], mh[4][2], ml[4][2];
#pragma unroll
            for (int mt = 0; mt < 2; mt++) {
                uint32_t off = (uint32_t)((nw * 32 + mt * 16 + rr + (mat & 1) * 8) * 144
                                          + kb + (mat >> 1) * 16);
                ldsm4(wh[mt], sWh + off);
                ldsm4(wl[mt], sWl + off);
            }
#pragma unroll
            for (int np = 0; np < 2; np++) {
                uint32_t off = (uint32_t)((mw * 32 + (np * 2 + (mat >> 1)) * 8 + rr) * 144
                                          + kb + (mat & 1) * 16);
                uint32_t t4[4];
                ldsm4(t4, sMh + off);
                mh[np*2][0] = t4[0]; mh[np*2][1] = t4[1];
                mh[np*2+1][0] = t4[2]; mh[np*2+1][1] = t4[3];
                ldsm4(t4, sMl + off);
                ml[np*2][0] = t4[0]; ml[np*2][1] = t4[1];
                ml[np*2+1][0] = t4[2]; ml[np*2+1][1] = t4[3];
            }
#pragma unroll
            for (int mt = 0; mt < 2; mt++)
#pragma unroll
                for (int nt = 0; nt < 4; nt++)
                    mma16816(acc[mt][nt], wh[mt], mh[nt]);
#pragma unroll
            for (int mt = 0; mt < 2; mt++)
#pragma unroll
                for (int nt = 0; nt < 4; nt++)
                    mma16816(acc[mt][nt], wh[mt], ml[nt]);
#pragma unroll
            for (int mt = 0; mt < 2; mt++)
#pragma unroll
                for (int nt = 0; nt < 4; nt++)
                    mma16816(acc[mt][nt], wl[mt], mh[nt]);
        }
        __syncthreads();
    }

    float* sOut = (float*)smem;
#pragma unroll
    for (int mt = 0; mt < 2; mt++)
#pragma unroll
        for (int nt = 0; nt < 4; nt++) {
            int n_loc = nw * 32 + mt * 16 + g;
            int m_loc = mw * 32 + nt * 8 + tig * 2;
            sOut[m_loc * 65 + n_loc]           = acc[mt][nt][0];
            sOut[(m_loc + 1) * 65 + n_loc]     = acc[mt][nt][1];
            sOut[m_loc * 65 + n_loc + 8]       = acc[mt][nt][2];
            sOut[(m_loc + 1) * 65 + n_loc + 8] = acc[mt][nt][3];
        }
    __syncthreads();

    if (MODE == 0) {
        for (int t = tid; t < 128 * 16; t += 256) {
            int m_loc = t >> 4, c4 = (t & 15) * 4;
            int m = mb0 + m_loc;
            int b = m / 3136, hw = m - b * 3136;
            int h = hw / 56, w = hw - h * 56;
            float2 a, c;
            a.x = sOut[m_loc * 65 + c4 + 0] + __ldg(&bias[nb0 + c4 + 0]);
            a.y = sOut[m_loc * 65 + c4 + 1] + __ldg(&bias[nb0 + c4 + 1]);
            c.x = sOut[m_loc * 65 + c4 + 2] + __ldg(&bias[nb0 + c4 + 2]);
            c.y = sOut[m_loc * 65 + c4 + 3] + __ldg(&bias[nb0 + c4 + 3]);
            __half2 h0 = __float22half2_rn(a);
            __half2 h1 = __float22half2_rn(c);
            uint2 st;
            st.x = *(uint32_t*)&h0;
            st.y = *(uint32_t*)&h1;
            *(uint2*)(g_vp + ((size_t)((b * 58 + h + 1) * 58 + (w + 1))) * 256
                      + nb0 + c4) = st;
        }
    } else if (MODE == 1) {
        int navail = NOM - nb0; if (navail > 64) navail = 64;
        if (navail > 0) {
            const int nq = navail >> 2;
            for (int t = tid; t < 128 * nq; t += 256) {
                int m_loc = t / nq, c4 = (t - m_loc * nq) * 4;
                int n = nb0 + c4;
                float4 v;
                float* sp = &sOut[m_loc * 65 + c4];
                v.x = sp[0] + ((n + 0 < NOFF) ? __ldg(&bias[n + 0]) : __ldg(&bias2[n + 0 - NOFF]));
                v.y = sp[1] + ((n + 1 < NOFF) ? __ldg(&bias[n + 1]) : __ldg(&bias2[n + 1 - NOFF]));
                v.z = sp[2] + ((n + 2 < NOFF) ? __ldg(&bias[n + 2]) : __ldg(&bias2[n + 2 - NOFF]));
                v.w = sp[3] + ((n + 3 < NOFF) ? __ldg(&bias[n + 3]) : __ldg(&bias2[n + 3 - NOFF]));
                *(float4*)(g_om + (size_t)(mb0 + m_loc) * 216 + n) = v;
            }
        }
    } else {
        for (int ni = wid; ni < 64; ni += 8) {
            int n = nb0 + ni;
            float kA = __ldg(&bn_g[n]) * rsqrtf(__ldg(&bn_var[n]) + 1e-5f);
            float kB = (__ldg(&bias[n]) - __ldg(&bn_mean[n])) * kA + __ldg(&bn_b[n]);
#pragma unroll
            for (int mh2 = 0; mh2 < 4; mh2++) {
                int m_loc = mh2 * 32 + lane;
                int m = mb0 + m_loc;
                int b = m / 3136, hw = m - b * 3136;
                float f = sOut[m_loc * 65 + ni] * kA + kB;
                float o = f / (1.f + expf(-f));
                Cout[((size_t)(b * 256 + n)) * 3136 + hw] = o;
            }
        }
    }
}

// ---------------------------------------------------------------------------
// Depthwise 3x3 conv (NCHW in) -> NHWC g_f (pre-LN).  (R15 loader, R14 compute)
// ---------------------------------------------------------------------------
__global__ __launch_bounds__(256)
void dwconv_kernel(const float* __restrict__ x,
                   const float* __restrict__ dw_w,
                   const float* __restrict__ dw_b)
{
    __shared__ float sx[32 * 177];   // [c]*177 + r*59 + col

    const int c0  = blockIdx.x * 32;
    const int h   = blockIdx.y;
    const int b   = blockIdx.z;
    const int tid = threadIdx.x;

    {
        const int lc = tid >> 3;
        const int s  = tid & 7;
        const float* xc = x + ((size_t)(b * 256 + c0 + lc)) * 3136;
        float* sc = sx + lc * 177;
#pragma unroll
        for (int r = 0; r < 3; r++) {
            int hh = h - 1 + r;
            bool hok = (hh >= 0) && (hh < 56);
            const float* xr = xc + hh * 56;
            float* sr = sc + r * 59;
#pragma unroll
            for (int j = 0; j < 8; j++) {
                int col = j * 8 + s;
                if (col < 58) {
                    int wwc = col - 1;
                    float v = (hok && wwc >= 0 && wwc < 56) ? xr[wwc] : 0.f;
                    sr[col] = v;
                }
            }
        }
    }

    const int c  = tid & 31;
    const int wg = tid >> 5;
    float wgt[9];
#pragma unroll
    for (int j = 0; j < 9; j++) wgt[j] = __ldg(&dw_w[(c0 + c) * 9 + j]);
    const float bias = __ldg(&dw_b[c0 + c]);
    __syncthreads();

    const int w0 = wg * 7;
    const float* base = sx + c * 177 + w0;

    float rowv[3][9];
#pragma unroll
    for (int r = 0; r < 3; r++)
#pragma unroll
        for (int j = 0; j < 9; j++)
            rowv[r][j] = base[r * 59 + j];

    float outv[7];
#pragma unroll
    for (int i = 0; i < 7; i++) {
        float a = bias;
#pragma unroll
        for (int r = 0; r < 3; r++)
#pragma unroll
            for (int j = 0; j < 3; j++)
                a = fmaf(rowv[r][i + j], wgt[r * 3 + j], a);
        outv[i] = a;
    }

    float* dst = g_f + ((size_t)((b * 56 + h) * 56 + w0)) * 256 + c0 + c;
#pragma unroll
    for (int i = 0; i < 7; i++) dst[(size_t)i * 256] = outv[i];
}

// ---------------------------------------------------------------------------
// LayerNorm (C=256) + exact GELU; warp-per-position; writes split bf16.
// ---------------------------------------------------------------------------
__global__ __launch_bounds__(256)
void ln_gelu_kernel(const float* __restrict__ ln_g,
                    const float* __restrict__ ln_b)
{
    const int warp = threadIdx.x >> 5, lane = threadIdx.x & 31;
    const int m = blockIdx.x * 8 + warp;
    const int k0 = lane * 8;

    const float* src = g_f + (size_t)m * 256 + k0;
    float4 v0 = *(const float4*)src;
    float4 v1 = *(const float4*)(src + 4);
    float e[8] = {v0.x, v0.y, v0.z, v0.w, v1.x, v1.y, v1.z, v1.w};

    float s = 0.f, s2 = 0.f;
#pragma unroll
    for (int j = 0; j < 8; j++) { s += e[j]; s2 += e[j] * e[j]; }
#pragma unroll
    for (int o = 16; o; o >>= 1) {
        s  += __shfl_xor_sync(0xffffffffu, s,  o);
        s2 += __shfl_xor_sync(0xffffffffu, s2, o);
    }
    float mean = s * (1.f / 256.f);
    float var  = s2 * (1.f / 256.f) - mean * mean;
    float rstd = rsqrtf(var + 1e-5f);

    uint32_t hi[4], lo[4];
#pragma unroll
    for (int j = 0; j < 4; j++) {
        float a = (e[2*j]   - mean) * rstd * __ldg(&ln_g[k0 + 2*j])   + __ldg(&ln_b[k0 + 2*j]);
        float b = (e[2*j+1] - mean) * rstd * __ldg(&ln_g[k0 + 2*j+1]) + __ldg(&ln_b[k0 + 2*j+1]);
        a = 0.5f * a * (1.f + erff(a * 0.70710678118654752f));
        b = 0.5f * b * (1.f + erff(b * 0.70710678118654752f));
        hi[j] = hi2(a, b); lo[j] = lo2(a, b);
    }
    *(uint4*)(g_fh + (size_t)m * 256 + k0) = make_uint4(hi[0], hi[1], hi[2], hi[3]);
    *(uint4*)(g_fl + (size_t)m * 256 + k0) = make_uint4(lo[0], lo[1], lo[2], lo[3]);
}

// ---------------------------------------------------------------------------
// Deformable sampling over fp16 vp.  Warp: qid=corner (4), ql=channel quad (8);
// each lane loads uint2 = 4 fp16 channels (8B).  Corner sum via shfl.
// ---------------------------------------------------------------------------
__global__ __launch_bounds__(256)
void sample_kernel()
{
    const int wi   = threadIdx.x >> 5;
    const int lane = threadIdx.x & 31;
    const int qid  = lane >> 3;       // corner 0..3
    const int ql   = lane & 7;        // channel quad 0..7
    const int m    = blockIdx.x * 8 + wi;
    const int g    = blockIdx.y;

    const int b    = m / 3136;
    const int hw   = m - b * 3136;
    const int h    = hw / 56;
    const int w    = hw - h * 56;

    const float* row = g_om + (size_t)m * 216;
    const float2* rowo = (const float2*)(row) + g * 9;

    float offx[9], offy[9], mk[9];
    float mx = -3.0e38f;
#pragma unroll
    for (int p = 0; p < 9; p++) {
        float2 o = rowo[p];
        offx[p] = o.x; offy[p] = o.y;
        mk[p]   = row[144 + g * 9 + p];
        mx = fmaxf(mx, mk[p]);
    }
    float sum = 0.f;
#pragma unroll
    for (int p = 0; p < 9; p++) { mk[p] = expf(mk[p] - mx); sum += mk[p]; }
    const float inv = 1.f / sum;

    const __half* vpg = g_vp + (size_t)b * 58 * 58 * 256 + g * 32 + ql * 4;

    float4 acc = make_float4(0.f, 0.f, 0.f, 0.f);

#pragma unroll
    for (int p = 0; p < 9; p++) {
        float px = (float)(w + (p / 3)) + offx[p];
        float py = (float)(h + (p % 3)) + offy[p];
        float x0f = floorf(px), y0f = floorf(py);
        float wx = px - x0f, wy = py - y0f;
        int x0 = (int)x0f, y0 = (int)y0f;
        int x1 = x0 + 1,   y1 = y0 + 1;
        float vx0 = (x0 >= 0 && x0 < 58) ? 1.f : 0.f;
        float vx1 = (x1 >= 0 && x1 < 58) ? 1.f : 0.f;
        float vy0 = (y0 >= 0 && y0 < 58) ? 1.f : 0.f;
        float vy1 = (y1 >= 0 && y1 < 58) ? 1.f : 0.f;
        int x0c = min(max(x0, 0), 57), x1c = min(max(x1, 0), 57);
        int y0c = min(max(y0, 0), 57), y1c = min(max(y1, 0), 57);

        const float mp = mk[p] * inv;
        float wgt; int yy, xx;
        if (qid == 0)      { wgt = (1.f - wx) * (1.f - wy) * vx0 * vy0; yy = y0c; xx = x0c; }
        else if (qid == 1) { wgt = wx * (1.f - wy) * vx1 * vy0;         yy = y0c; xx = x1c; }
        else if (qid == 2) { wgt = (1.f - wx) * wy * vx0 * vy1;         yy = y1c; xx = x0c; }
        else               { wgt = wx * wy * vx1 * vy1;                 yy = y1c; xx = x1c; }
        wgt *= mp;

        uint2 raw = *(const uint2*)(vpg + (size_t)(yy * 58 + xx) * 256);
        __half2 h0 = *(__half2*)&raw.x;
        __half2 h1 = *(__half2*)&raw.y;
        float2 f0 = __half22float2(h0);
        float2 f1 = __half22float2(h1);
        acc.x = fmaf(wgt, f0.x, acc.x);
        acc.y = fmaf(wgt, f0.y, acc.y);
        acc.z = fmaf(wgt, f1.x, acc.z);
        acc.w = fmaf(wgt, f1.y, acc.w);
    }

#pragma unroll
    for (int o = 8; o <= 16; o <<= 1) {
        acc.x += __shfl_xor_sync(0xffffffffu, acc.x, o);
        acc.y += __shfl_xor_sync(0xffffffffu, acc.y, o);
        acc.z += __shfl_xor_sync(0xffffffffu, acc.z, o);
        acc.w += __shfl_xor_sync(0xffffffffu, acc.w, o);
    }

    if (qid == 0) {
        int c = g * 32 + ql * 4;
        uint2 hv, lv;
        hv.x = hi2(acc.x, acc.y); hv.y = hi2(acc.z, acc.w);
        lv.x = lo2(acc.x, acc.y); lv.y = lo2(acc.z, acc.w);
        *(uint2*)(g_sh + (size_t)m * 256 + c) = hv;
        *(uint2*)(g_sl + (size_t)m * 256 + c) = lv;
    }
}

// ---------------------------------------------------------------------------
extern "C" void kernel_launch(void* const* d_in, const int* in_sizes, int n_in,
                              void* d_out, int out_size)
{
    const float* x      = (const float*)d_in[0];
    const float* b_in   = (const float*)d_in[2];
    const float* dw_w   = (const float*)d_in[3];
    const float* dw_b   = (const float*)d_in[4];
    const float* ln_g   = (const float*)d_in[5];
    const float* ln_b   = (const float*)d_in[6];
    const float* b_off  = (const float*)d_in[8];
    const float* b_mask = (const float*)d_in[10];
    const float* b_out  = (const float*)d_in[12];
    const float* bn_g   = (const float*)d_in[13];
    const float* bn_b   = (const float*)d_in[14];
    const float* bn_mean= (const float*)d_in[15];
    const float* bn_var = (const float*)d_in[16];
    float* out = (float*)d_out;

    cudaFuncSetAttribute(gemm_mma<0>, cudaFuncAttributeMaxDynamicSharedMemorySize, SMEM_GEMM);
    cudaFuncSetAttribute(gemm_mma<1>, cudaFuncAttributeMaxDynamicSharedMemorySize, SMEM_GEMM);
    cudaFuncSetAttribute(gemm_mma<2>, cudaFuncAttributeMaxDynamicSharedMemorySize, SMEM_GEMM);

    dim3 ggrid(4, 196);

    prep_weights<<<192, 256>>>((const float*)d_in[1], (const float*)d_in[7],
                               (const float*)d_in[9], (const float*)d_in[11]);
    prep_x<<<784, 256>>>(x);
    dwconv_kernel<<<dim3(8, 56, 8), 256>>>(x, dw_w, dw_b);
    ln_gelu_kernel<<<3136, 256>>>(ln_g, ln_b);
    zero_border_kernel<<<228 * 8, 256>>>();
    // input projection -> padded vp (NHWC fp16)
    gemm_mma<0><<<ggrid, 256, SMEM_GEMM>>>(b_in, nullptr, nullptr,
                                           nullptr, nullptr, nullptr, nullptr);
    gemm_mma<1><<<ggrid, 256, SMEM_GEMM>>>(b_off, b_mask, nullptr,
                                           nullptr, nullptr, nullptr, nullptr);
    // deformable bilinear sampling + mask aggregation
    sample_kernel<<<dim3(3136, 8), 256>>>();
    // output projection + BN + SiLU -> NCHW
    gemm_mma<2><<<ggrid, 256, SMEM_GEMM>>>(b_out, nullptr, out,
                                           bn_g, bn_b, bn_mean, bn_var);
}

// round 17
// speedup vs baseline: 1.3431x; 1.3431x over previous
#include <cuda_runtime.h>
#include <cuda_bf16.h>
#include <cuda_fp16.h>
#include <math.h>
#include <stdint.h>

// Problem constants
#define BB    8
#define CC    256
#define HH    56
#define WW    56
#define HIN   58
#define WIN   58
#define MTOT  25088      // B*H*W
#define NOFF  144
#define NMSK  72
#define NOM   216

// Scratch (device globals; no runtime allocation allowed)
__device__ __half g_vp[BB*HIN*WIN*CC];       // padded projected features, NHWC fp16
__device__ float g_f [MTOT*CC];              // dwconv output (pre-LN), NHWC fp32
__device__ float g_om[MTOT*NOM];             // [offset(144) | mask(72)] logits
__device__ uint2 g_meta[MTOT*8*9*4];         // per-tap: 4 corners x {addr, wgt}  (58MB)
__device__ __nv_bfloat16 g_xh[MTOT*CC];      // x-proj activations hi   [m][k]
__device__ __nv_bfloat16 g_xl[MTOT*CC];
__device__ __nv_bfloat16 g_fh[MTOT*CC];      // LN/GELU activations hi
__device__ __nv_bfloat16 g_fl[MTOT*CC];
__device__ __nv_bfloat16 g_sh[MTOT*CC];      // sampled activations hi
__device__ __nv_bfloat16 g_sl[MTOT*CC];
__device__ __nv_bfloat16 g_wth[3*65536];     // weights^T [which][n][k], hi
__device__ __nv_bfloat16 g_wtl[3*65536];     // weights^T lo

// ---------------------------------------------------------------------------
// fp32 -> bf16 hi/lo split helpers
// ---------------------------------------------------------------------------
__device__ __forceinline__ uint32_t hibits(float v) {
    uint32_t u = __float_as_uint(v);
    return (u + 0x7FFFu + ((u >> 16) & 1u)) & 0xFFFF0000u;
}
__device__ __forceinline__ uint32_t hi2(float a, float b) {
    return (hibits(a) >> 16) | (hibits(b) & 0xFFFF0000u);
}
__device__ __forceinline__ uint32_t lo2(float a, float b) {
    float la = a - __uint_as_float(hibits(a));
    float lb = b - __uint_as_float(hibits(b));
    uint32_t r;
    asm("cvt.rn.satfinite.bf16x2.f32 %0, %1, %2;" : "=r"(r) : "f"(lb), "f"(la));
    return r;
}
__device__ __forceinline__ void split1(float v, __nv_bfloat16* ph, __nv_bfloat16* pl) {
    uint32_t hb = hibits(v);
    __nv_bfloat16_raw hr; hr.x = (unsigned short)(hb >> 16);
    *ph = __nv_bfloat16(hr);
    *pl = __float2bfloat16(v - __uint_as_float(hb));
}

// mma.sync m16n8k16 bf16 -> f32
__device__ __forceinline__ void mma16816(float* c, const uint32_t* a, const uint32_t* b) {
    asm volatile(
        "mma.sync.aligned.m16n8k16.row.col.f32.bf16.bf16.f32 "
        "{%0,%1,%2,%3}, {%4,%5,%6,%7}, {%8,%9}, {%0,%1,%2,%3};"
        : "+f"(c[0]), "+f"(c[1]), "+f"(c[2]), "+f"(c[3])
        : "r"(a[0]), "r"(a[1]), "r"(a[2]), "r"(a[3]), "r"(b[0]), "r"(b[1]));
}

// ldmatrix x4
__device__ __forceinline__ void ldsm4(uint32_t* r, uint32_t a) {
    asm volatile("ldmatrix.sync.aligned.m8n8.x4.shared.b16 {%0,%1,%2,%3}, [%4];"
        : "=r"(r[0]), "=r"(r[1]), "=r"(r[2]), "=r"(r[3]) : "r"(a));
}

__device__ __forceinline__ uint32_t smem_u32(const void* p) {
    uint32_t a;
    asm("{ .reg .u64 t; cvta.to.shared.u64 t, %1; cvt.u32.u64 %0, t; }"
        : "=r"(a) : "l"(p));
    return a;
}
__device__ __forceinline__ void cpasync16(uint32_t dst, const void* src) {
    asm volatile("cp.async.cg.shared.global [%0], [%1], 16;" :: "r"(dst), "l"(src));
}
#define CP_COMMIT()  asm volatile("cp.async.commit_group;" ::: "memory")
#define CP_WAIT(n)   asm volatile("cp.async.wait_group %0;" :: "n"(n) : "memory")

// ---------------------------------------------------------------------------
// Weight prep with 32x32 smem transpose.
// ---------------------------------------------------------------------------
__global__ __launch_bounds__(256)
void prep_weights(const float* __restrict__ w_in,
                  const float* __restrict__ w_off,
                  const float* __restrict__ w_mask,
                  const float* __restrict__ w_out)
{
    __shared__ float s[32][33];
    const int which = blockIdx.x >> 6;
    const int t = blockIdx.x & 63;
    const int n0 = (t & 7) * 32, k0 = (t >> 3) * 32;
    const int tid = threadIdx.x;
    const int col = tid & 31, rowq = tid >> 5;

#pragma unroll
    for (int i = 0; i < 4; i++) {
        int kk = rowq + i * 8;
        int k = k0 + kk, n = n0 + col;
        float v;
        if (which == 0)      v = w_in[k * 256 + n];
        else if (which == 1) v = (n < NOFF) ? w_off[k * NOFF + n]
                               : (n < NOM) ? w_mask[k * NMSK + (n - NOFF)] : 0.f;
        else                 v = w_out[k * 256 + n];
        s[kk][col] = v;
    }
    __syncthreads();
#pragma unroll
    for (int i = 0; i < 4; i++) {
        int nn = rowq + i * 8;
        float v = s[col][nn];
        size_t idx = (size_t)which * 65536 + (size_t)(n0 + nn) * 256 + k0 + col;
        split1(v, &g_wth[idx], &g_wtl[idx]);
    }
}

// ---------------------------------------------------------------------------
// x (NCHW) -> g_xh/g_xl [m][k] via smem transpose.  grid = 784
// ---------------------------------------------------------------------------
__global__ __launch_bounds__(256)
void prep_x(const float* __restrict__ x)
{
    __shared__ float s[32][257];
    const int mb = blockIdx.x * 32;
    const int b = mb / 3136, hw0 = mb % 3136;
    const int lane = threadIdx.x & 31, kw = threadIdx.x >> 5;
#pragma unroll
    for (int p = 0; p < 32; p++) {
        int k = p * 8 + kw;
        s[lane][k] = x[((size_t)(b * 256 + k)) * 3136 + hw0 + lane];
    }
    __syncthreads();
    const int row = threadIdx.x >> 3, seg = threadIdx.x & 7;
    const int m = mb + row, k0 = seg * 32;
    uint32_t hi[16], lo[16];
#pragma unroll
    for (int j = 0; j < 16; j++) {
        float a = s[row][k0 + 2 * j], bv = s[row][k0 + 2 * j + 1];
        hi[j] = hi2(a, bv); lo[j] = lo2(a, bv);
    }
    uint4* dh = (uint4*)(g_xh + (size_t)m * 256 + k0);
    uint4* dl = (uint4*)(g_xl + (size_t)m * 256 + k0);
#pragma unroll
    for (int q = 0; q < 4; q++) {
        dh[q] = make_uint4(hi[4*q], hi[4*q+1], hi[4*q+2], hi[4*q+3]);
        dl[q] = make_uint4(lo[4*q], lo[4*q+1], lo[4*q+2], lo[4*q+3]);
    }
}

// ---------------------------------------------------------------------------
// Zero only the padding ring of g_vp (fp16: 2 channels per uint32 store).
// ---------------------------------------------------------------------------
__global__ void zero_border_kernel() {
    int cell = blockIdx.x;            // 0..228*8-1
    int b = cell / 228, r = cell % 228;
    int h, w;
    if (r < 58)        { h = 0;  w = r; }
    else if (r < 116)  { h = 57; w = r - 58; }
    else if (r < 172)  { h = r - 116 + 1; w = 0; }
    else               { h = r - 172 + 1; w = 57; }
    if (threadIdx.x < 128)
        ((uint32_t*)(g_vp + ((size_t)((b * 58 + h) * 58 + w)) * 256))[threadIdx.x] = 0u;
}

// ---------------------------------------------------------------------------
// Tensor-core GEMM.  Activation buffers selected by MODE inside device code.
// ---------------------------------------------------------------------------
#define SW_BYTES   9216    // 64 rows * 144 B
#define SM_BYTES   18432   // 128 rows * 144 B
#define STG_BYTES  55296   // 2*(SW+SM)
#define SMEM_GEMM  (2 * STG_BYTES)

template<int MODE>
__global__ __launch_bounds__(256, 2)
void gemm_mma(const float* __restrict__ bias,
              const float* __restrict__ bias2,
              float* __restrict__ Cout,
              const float* __restrict__ bn_g, const float* __restrict__ bn_b,
              const float* __restrict__ bn_mean, const float* __restrict__ bn_var)
{
    extern __shared__ char smem[];
    const uint32_t smem_b = smem_u32(smem);

    const int tid = threadIdx.x, wid = tid >> 5, lane = tid & 31;
    const int g = lane >> 2, tig = lane & 3;
    const int mat = lane >> 3, rr = lane & 7;
    const int nb0 = blockIdx.x * 64, mb0 = blockIdx.y * 128;
    const int nw = wid & 1;
    const int mw = wid >> 1;

    const __nv_bfloat16* wth = g_wth + MODE * 65536;
    const __nv_bfloat16* wtl = g_wtl + MODE * 65536;
    const __nv_bfloat16* ah = (MODE == 0) ? g_xh : (MODE == 1) ? g_fh : g_sh;
    const __nv_bfloat16* al = (MODE == 0) ? g_xl : (MODE == 1) ? g_fl : g_sl;

    float acc[2][4][4];
#pragma unroll
    for (int a = 0; a < 2; a++)
#pragma unroll
        for (int b = 0; b < 4; b++)
#pragma unroll
            for (int c = 0; c < 4; c++) acc[a][b][c] = 0.f;

    auto stage = [&](int buf, int chv) {
        const int k0c = chv * 64;
        const uint32_t base = smem_b + buf * STG_BYTES;
#pragma unroll
        for (int i = 0; i < 2; i++) {
            int idx = i * 256 + tid;
            int r = idx >> 3, seg = idx & 7;
            uint32_t so = base + (uint32_t)(r * 144 + seg * 16);
            size_t wof = (size_t)(nb0 + r) * 256 + k0c + seg * 8;
            cpasync16(so,            wth + wof);
            cpasync16(so + SW_BYTES, wtl + wof);
        }
#pragma unroll
        for (int i = 0; i < 4; i++) {
            int idx = i * 256 + tid;
            int r = idx >> 3, seg = idx & 7;
            uint32_t so = base + 2 * SW_BYTES + (uint32_t)(r * 144 + seg * 16);
            size_t mof = (size_t)(mb0 + r) * 256 + k0c + seg * 8;
            cpasync16(so,            ah + mof);
            cpasync16(so + SM_BYTES, al + mof);
        }
        CP_COMMIT();
    };

    stage(0, 0);

    for (int chv = 0; chv < 4; chv++) {
        if (chv + 1 < 4) { stage((chv + 1) & 1, chv + 1); CP_WAIT(1); }
        else             { CP_WAIT(0); }
        __syncthreads();

        const uint32_t sbuf = smem_b + (chv & 1) * STG_BYTES;
        const uint32_t sWh = sbuf;
        const uint32_t sWl = sbuf + SW_BYTES;
        const uint32_t sMh = sbuf + 2 * SW_BYTES;
        const uint32_t sMl = sbuf + 2 * SW_BYTES + SM_BYTES;

#pragma unroll
        for (int ks = 0; ks < 4; ks++) {
            const int kb = ks * 32;
            uint32_t wh[2][4], wl[2][4], mh[4][2], ml[4][2];
#pragma unroll
            for (int mt = 0; mt < 2; mt++) {
                uint32_t off = (uint32_t)((nw * 32 + mt * 16 + rr + (mat & 1) * 8) * 144
                                          + kb + (mat >> 1) * 16);
                ldsm4(wh[mt], sWh + off);
                ldsm4(wl[mt], sWl + off);
            }
#pragma unroll
            for (int np = 0; np < 2; np++) {
                uint32_t off = (uint32_t)((mw * 32 + (np * 2 + (mat >> 1)) * 8 + rr) * 144
                                          + kb + (mat & 1) * 16);
                uint32_t t4[4];
                ldsm4(t4, sMh + off);
                mh[np*2][0] = t4[0]; mh[np*2][1] = t4[1];
                mh[np*2+1][0] = t4[2]; mh[np*2+1][1] = t4[3];
                ldsm4(t4, sMl + off);
                ml[np*2][0] = t4[0]; ml[np*2][1] = t4[1];
                ml[np*2+1][0] = t4[2]; ml[np*2+1][1] = t4[3];
            }
#pragma unroll
            for (int mt = 0; mt < 2; mt++)
#pragma unroll
                for (int nt = 0; nt < 4; nt++)
                    mma16816(acc[mt][nt], wh[mt], mh[nt]);
#pragma unroll
            for (int mt = 0; mt < 2; mt++)
#pragma unroll
                for (int nt = 0; nt < 4; nt++)
                    mma16816(acc[mt][nt], wh[mt], ml[nt]);
#pragma unroll
            for (int mt = 0; mt < 2; mt++)
#pragma unroll
                for (int nt = 0; nt < 4; nt++)
                    mma16816(acc[mt][nt], wl[mt], mh[nt]);
        }
        __syncthreads();
    }

    float* sOut = (float*)smem;
#pragma unroll
    for (int mt = 0; mt < 2; mt++)
#pragma unroll
        for (int nt = 0; nt < 4; nt++) {
            int n_loc = nw * 32 + mt * 16 + g;
            int m_loc = mw * 32 + nt * 8 + tig * 2;
            sOut[m_loc * 65 + n_loc]           = acc[mt][nt][0];
            sOut[(m_loc + 1) * 65 + n_loc]     = acc[mt][nt][1];
            sOut[m_loc * 65 + n_loc + 8]       = acc[mt][nt][2];
            sOut[(m_loc + 1) * 65 + n_loc + 8] = acc[mt][nt][3];
        }
    __syncthreads();

    if (MODE == 0) {
        for (int t = tid; t < 128 * 16; t += 256) {
            int m_loc = t >> 4, c4 = (t & 15) * 4;
            int m = mb0 + m_loc;
            int b = m / 3136, hw = m - b * 3136;
            int h = hw / 56, w = hw - h * 56;
            float2 a, c;
            a.x = sOut[m_loc * 65 + c4 + 0] + __ldg(&bias[nb0 + c4 + 0]);
            a.y = sOut[m_loc * 65 + c4 + 1] + __ldg(&bias[nb0 + c4 + 1]);
            c.x = sOut[m_loc * 65 + c4 + 2] + __ldg(&bias[nb0 + c4 + 2]);
            c.y = sOut[m_loc * 65 + c4 + 3] + __ldg(&bias[nb0 + c4 + 3]);
            __half2 h0 = __float22half2_rn(a);
            __half2 h1 = __float22half2_rn(c);
            uint2 st;
            st.x = *(uint32_t*)&h0;
            st.y = *(uint32_t*)&h1;
            *(uint2*)(g_vp + ((size_t)((b * 58 + h + 1) * 58 + (w + 1))) * 256
                      + nb0 + c4) = st;
        }
    } else if (MODE == 1) {
        int navail = NOM - nb0; if (navail > 64) navail = 64;
        if (navail > 0) {
            const int nq = navail >> 2;
            for (int t = tid; t < 128 * nq; t += 256) {
                int m_loc = t / nq, c4 = (t - m_loc * nq) * 4;
                int n = nb0 + c4;
                float4 v;
                float* sp = &sOut[m_loc * 65 + c4];
                v.x = sp[0] + ((n + 0 < NOFF) ? __ldg(&bias[n + 0]) : __ldg(&bias2[n + 0 - NOFF]));
                v.y = sp[1] + ((n + 1 < NOFF) ? __ldg(&bias[n + 1]) : __ldg(&bias2[n + 1 - NOFF]));
                v.z = sp[2] + ((n + 2 < NOFF) ? __ldg(&bias[n + 2]) : __ldg(&bias2[n + 2 - NOFF]));
                v.w = sp[3] + ((n + 3 < NOFF) ? __ldg(&bias[n + 3]) : __ldg(&bias2[n + 3 - NOFF]));
                *(float4*)(g_om + (size_t)(mb0 + m_loc) * 216 + n) = v;
            }
        }
    } else {
        for (int ni = wid; ni < 64; ni += 8) {
            int n = nb0 + ni;
            float kA = __ldg(&bn_g[n]) * rsqrtf(__ldg(&bn_var[n]) + 1e-5f);
            float kB = (__ldg(&bias[n]) - __ldg(&bn_mean[n])) * kA + __ldg(&bn_b[n]);
#pragma unroll
            for (int mh2 = 0; mh2 < 4; mh2++) {
                int m_loc = mh2 * 32 + lane;
                int m = mb0 + m_loc;
                int b = m / 3136, hw = m - b * 3136;
                float f = sOut[m_loc * 65 + ni] * kA + kB;
                float o = f / (1.f + expf(-f));
                Cout[((size_t)(b * 256 + n)) * 3136 + hw] = o;
            }
        }
    }
}

// ---------------------------------------------------------------------------
// Depthwise 3x3 conv (NCHW in) -> NHWC g_f (pre-LN).  (R15 loader, R14 compute)
// ---------------------------------------------------------------------------
__global__ __launch_bounds__(256)
void dwconv_kernel(const float* __restrict__ x,
                   const float* __restrict__ dw_w,
                   const float* __restrict__ dw_b)
{
    __shared__ float sx[32 * 177];   // [c]*177 + r*59 + col

    const int c0  = blockIdx.x * 32;
    const int h   = blockIdx.y;
    const int b   = blockIdx.z;
    const int tid = threadIdx.x;

    {
        const int lc = tid >> 3;
        const int s  = tid & 7;
        const float* xc = x + ((size_t)(b * 256 + c0 + lc)) * 3136;
        float* sc = sx + lc * 177;
#pragma unroll
        for (int r = 0; r < 3; r++) {
            int hh = h - 1 + r;
            bool hok = (hh >= 0) && (hh < 56);
            const float* xr = xc + hh * 56;
            float* sr = sc + r * 59;
#pragma unroll
            for (int j = 0; j < 8; j++) {
                int col = j * 8 + s;
                if (col < 58) {
                    int wwc = col - 1;
                    float v = (hok && wwc >= 0 && wwc < 56) ? xr[wwc] : 0.f;
                    sr[col] = v;
                }
            }
        }
    }

    const int c  = tid & 31;
    const int wg = tid >> 5;
    float wgt[9];
#pragma unroll
    for (int j = 0; j < 9; j++) wgt[j] = __ldg(&dw_w[(c0 + c) * 9 + j]);
    const float bias = __ldg(&dw_b[c0 + c]);
    __syncthreads();

    const int w0 = wg * 7;
    const float* base = sx + c * 177 + w0;

    float rowv[3][9];
#pragma unroll
    for (int r = 0; r < 3; r++)
#pragma unroll
        for (int j = 0; j < 9; j++)
            rowv[r][j] = base[r * 59 + j];

    float outv[7];
#pragma unroll
    for (int i = 0; i < 7; i++) {
        float a = bias;
#pragma unroll
        for (int r = 0; r < 3; r++)
#pragma unroll
            for (int j = 0; j < 3; j++)
                a = fmaf(rowv[r][i + j], wgt[r * 3 + j], a);
        outv[i] = a;
    }

    float* dst = g_f + ((size_t)((b * 56 + h) * 56 + w0)) * 256 + c0 + c;
#pragma unroll
    for (int i = 0; i < 7; i++) dst[(size_t)i * 256] = outv[i];
}

// ---------------------------------------------------------------------------
// LayerNorm (C=256) + exact GELU; warp-per-position; writes split bf16.
// ---------------------------------------------------------------------------
__global__ __launch_bounds__(256)
void ln_gelu_kernel(const float* __restrict__ ln_g,
                    const float* __restrict__ ln_b)
{
    const int warp = threadIdx.x >> 5, lane = threadIdx.x & 31;
    const int m = blockIdx.x * 8 + warp;
    const int k0 = lane * 8;

    const float* src = g_f + (size_t)m * 256 + k0;
    float4 v0 = *(const float4*)src;
    float4 v1 = *(const float4*)(src + 4);
    float e[8] = {v0.x, v0.y, v0.z, v0.w, v1.x, v1.y, v1.z, v1.w};

    float s = 0.f, s2 = 0.f;
#pragma unroll
    for (int j = 0; j < 8; j++) { s += e[j]; s2 += e[j] * e[j]; }
#pragma unroll
    for (int o = 16; o; o >>= 1) {
        s  += __shfl_xor_sync(0xffffffffu, s,  o);
        s2 += __shfl_xor_sync(0xffffffffu, s2, o);
    }
    float mean = s * (1.f / 256.f);
    float var  = s2 * (1.f / 256.f) - mean * mean;
    float rstd = rsqrtf(var + 1e-5f);

    uint32_t hi[4], lo[4];
#pragma unroll
    for (int j = 0; j < 4; j++) {
        float a = (e[2*j]   - mean) * rstd * __ldg(&ln_g[k0 + 2*j])   + __ldg(&ln_b[k0 + 2*j]);
        float b = (e[2*j+1] - mean) * rstd * __ldg(&ln_g[k0 + 2*j+1]) + __ldg(&ln_b[k0 + 2*j+1]);
        a = 0.5f * a * (1.f + erff(a * 0.70710678118654752f));
        b = 0.5f * b * (1.f + erff(b * 0.70710678118654752f));
        hi[j] = hi2(a, b); lo[j] = lo2(a, b);
    }
    *(uint4*)(g_fh + (size_t)m * 256 + k0) = make_uint4(hi[0], hi[1], hi[2], hi[3]);
    *(uint4*)(g_fl + (size_t)m * 256 + k0) = make_uint4(lo[0], lo[1], lo[2], lo[3]);
}

// ---------------------------------------------------------------------------
// Sampling meta: one thread per (m, g, p) tap.  Computes softmax weight,
// bilinear corner weights (incl. validity) and 4 resolved fp16-element
// addresses into g_vp.  block = 288 threads = 4 positions x 72 taps.
// ---------------------------------------------------------------------------
__global__ __launch_bounds__(288)
void meta_kernel()
{
    const int tid = threadIdx.x;
    const int lm = tid / 72, r = tid - lm * 72;
    const int g = r / 9, p = r - g * 9;
    const int m = blockIdx.x * 4 + lm;

    const int b = m / 3136, hw = m - b * 3136;
    const int h = hw / 56, w = hw - h * 56;

    const float* row = g_om + (size_t)m * 216;

    // softmax over the 9 taps of (m, g)
    float mx = -3.0e38f;
    float lg[9];
#pragma unroll
    for (int j = 0; j < 9; j++) {
        lg[j] = row[144 + g * 9 + j];
        mx = fmaxf(mx, lg[j]);
    }
    float sum = 0.f;
#pragma unroll
    for (int j = 0; j < 9; j++) sum += expf(lg[j] - mx);
    const float mp = expf(lg[p] - mx) / sum;

    const float offx = row[g * 18 + 2 * p];
    const float offy = row[g * 18 + 2 * p + 1];

    float px = (float)(w + (p / 3)) + offx;
    float py = (float)(h + (p % 3)) + offy;
    float x0f = floorf(px), y0f = floorf(py);
    float wx = px - x0f, wy = py - y0f;
    int x0 = (int)x0f, y0 = (int)y0f;
    int x1 = x0 + 1,   y1 = y0 + 1;
    float vx0 = (x0 >= 0 && x0 < 58) ? 1.f : 0.f;
    float vx1 = (x1 >= 0 && x1 < 58) ? 1.f : 0.f;
    float vy0 = (y0 >= 0 && y0 < 58) ? 1.f : 0.f;
    float vy1 = (y1 >= 0 && y1 < 58) ? 1.f : 0.f;
    int x0c = min(max(x0, 0), 57), x1c = min(max(x1, 0), 57);
    int y0c = min(max(y0, 0), 57), y1c = min(max(y1, 0), 57);

    float w00 = (1.f - wx) * (1.f - wy) * vx0 * vy0 * mp;
    float w01 = wx * (1.f - wy) * vx1 * vy0 * mp;
    float w10 = (1.f - wx) * wy * vx0 * vy1 * mp;
    float w11 = wx * wy * vx1 * vy1 * mp;

    // fp16-element index into g_vp (lane adds ql*4 later)
    const uint32_t base = (uint32_t)(b * 3364) * 256 + g * 32;
    uint32_t a00 = base + (uint32_t)(y0c * 58 + x0c) * 256;
    uint32_t a01 = base + (uint32_t)(y0c * 58 + x1c) * 256;
    uint32_t a10 = base + (uint32_t)(y1c * 58 + x0c) * 256;
    uint32_t a11 = base + (uint32_t)(y1c * 58 + x1c) * 256;

    uint4* dst = (uint4*)(g_meta + ((size_t)(m * 8 + g) * 9 + p) * 4);
    dst[0] = make_uint4(a00, __float_as_uint(w00), a01, __float_as_uint(w01));
    dst[1] = make_uint4(a10, __float_as_uint(w10), a11, __float_as_uint(w11));
}

// ---------------------------------------------------------------------------
// Lean gather: warp per (m,g); lane (qid=corner, ql=quad).  Per tap: one
// broadcast meta load + one fp16 gather + 4 FMA.  Corner sum via shfl.
// ---------------------------------------------------------------------------
__global__ __launch_bounds__(256)
void sample_kernel()
{
    const int wi   = threadIdx.x >> 5;
    const int lane = threadIdx.x & 31;
    const int qid  = lane >> 3;       // corner 0..3
    const int ql   = lane & 7;        // channel quad 0..7
    const int m    = blockIdx.x * 8 + wi;
    const int g    = blockIdx.y;

    const uint2* meta = g_meta + (size_t)(m * 8 + g) * 36 + qid;

    float4 acc = make_float4(0.f, 0.f, 0.f, 0.f);

#pragma unroll
    for (int p = 0; p < 9; p++) {
        uint2 mw = meta[p * 4];
        float wgt = __uint_as_float(mw.y);
        uint2 raw = *(const uint2*)(g_vp + mw.x + ql * 4);
        __half2 h0 = *(__half2*)&raw.x;
        __half2 h1 = *(__half2*)&raw.y;
        float2 f0 = __half22float2(h0);
        float2 f1 = __half22float2(h1);
        acc.x = fmaf(wgt, f0.x, acc.x);
        acc.y = fmaf(wgt, f0.y, acc.y);
        acc.z = fmaf(wgt, f1.x, acc.z);
        acc.w = fmaf(wgt, f1.y, acc.w);
    }

#pragma unroll
    for (int o = 8; o <= 16; o <<= 1) {
        acc.x += __shfl_xor_sync(0xffffffffu, acc.x, o);
        acc.y += __shfl_xor_sync(0xffffffffu, acc.y, o);
        acc.z += __shfl_xor_sync(0xffffffffu, acc.z, o);
        acc.w += __shfl_xor_sync(0xffffffffu, acc.w, o);
    }

    if (qid == 0) {
        int c = g * 32 + ql * 4;
        uint2 hv, lv;
        hv.x = hi2(acc.x, acc.y); hv.y = hi2(acc.z, acc.w);
        lv.x = lo2(acc.x, acc.y); lv.y = lo2(acc.z, acc.w);
        *(uint2*)(g_sh + (size_t)m * 256 + c) = hv;
        *(uint2*)(g_sl + (size_t)m * 256 + c) = lv;
    }
}

// ---------------------------------------------------------------------------
extern "C" void kernel_launch(void* const* d_in, const int* in_sizes, int n_in,
                              void* d_out, int out_size)
{
    const float* x      = (const float*)d_in[0];
    const float* b_in   = (const float*)d_in[2];
    const float* dw_w   = (const float*)d_in[3];
    const float* dw_b   = (const float*)d_in[4];
    const float* ln_g   = (const float*)d_in[5];
    const float* ln_b   = (const float*)d_in[6];
    const float* b_off  = (const float*)d_in[8];
    const float* b_mask = (const float*)d_in[10];
    const float* b_out  = (const float*)d_in[12];
    const float* bn_g   = (const float*)d_in[13];
    const float* bn_b   = (const float*)d_in[14];
    const float* bn_mean= (const float*)d_in[15];
    const float* bn_var = (const float*)d_in[16];
    float* out = (float*)d_out;

    cudaFuncSetAttribute(gemm_mma<0>, cudaFuncAttributeMaxDynamicSharedMemorySize, SMEM_GEMM);
    cudaFuncSetAttribute(gemm_mma<1>, cudaFuncAttributeMaxDynamicSharedMemorySize, SMEM_GEMM);
    cudaFuncSetAttribute(gemm_mma<2>, cudaFuncAttributeMaxDynamicSharedMemorySize, SMEM_GEMM);

    dim3 ggrid(4, 196);

    prep_weights<<<192, 256>>>((const float*)d_in[1], (const float*)d_in[7],
                               (const float*)d_in[9], (const float*)d_in[11]);
    prep_x<<<784, 256>>>(x);
    dwconv_kernel<<<dim3(8, 56, 8), 256>>>(x, dw_w, dw_b);
    ln_gelu_kernel<<<3136, 256>>>(ln_g, ln_b);
    zero_border_kernel<<<228 * 8, 256>>>();
    // input projection -> padded vp (NHWC fp16)
    gemm_mma<0><<<ggrid, 256, SMEM_GEMM>>>(b_in, nullptr, nullptr,
                                           nullptr, nullptr, nullptr, nullptr);
    gemm_mma<1><<<ggrid, 256, SMEM_GEMM>>>(b_off, b_mask, nullptr,
                                           nullptr, nullptr, nullptr, nullptr);
    // sampling meta (softmax + bilinear weights + resolved addresses)
    meta_kernel<<<6272, 288>>>();
    // lean gather + mask aggregation
    sample_kernel<<<dim3(3136, 8), 256>>>();
    // output projection + BN + SiLU -> NCHW
    gemm_mma<2><<<ggrid, 256, SMEM_GEMM>>>(b_out, nullptr, out,
                                           bn_g, bn_b, bn_mean, bn_var);
}